// round 16
// baseline (speedup 1.0000x reference)
#include <cuda_runtime.h>
#include <math.h>

#define N 512
#define D 256
#define BT 32
#define NBLK_D 136            // 16*17/2 triangle of 32x32 tiles
#define NBLK_T 512            // one anchor per triplet block
#define FULL 0xFFFFFFFFu

// __device__ scratch (allocation-free rule; zero-init at load)
__device__ float g_dist[N * N];
__device__ int   g_cls[64 * 32];      // per class: [0]=count, [1..]=members
__device__ float g_psum[NBLK_T];
__device__ float g_pcnt[NBLK_T];
__device__ int   g_done = 0;

// ---------------------------------------------------------------------------
// Kernel 1: fused sq-norms + symmetric distances (R6/R15-proven core).
// Diagonal blocks additionally emit class member lists (warp per class).
// ---------------------------------------------------------------------------
__global__ void __launch_bounds__(256)
dist_kernel(const float* __restrict__ x, const int* __restrict__ labels) {
    __shared__ float As[BT][34];      // [k][m]
    __shared__ float Bs[BT][34];      // [k][n]
    __shared__ float sqi[BT];
    __shared__ float sqj[BT];

    const int t = threadIdx.x;        // 0..255
    const int lane = t & 31;
    const int w = t >> 5;             // 0..7

    // let the dependent (triplet) grid start its prologue early
    cudaTriggerProgrammaticLaunchCompletion();

    // triangle decode (bi >= bj)
    int b = blockIdx.x;
    int bi = (int)((sqrtf(8.f * (float)b + 1.f) - 1.f) * 0.5f);
    while ((bi + 1) * (bi + 2) / 2 <= b) bi++;
    while (bi * (bi + 1) / 2 > b) bi--;
    const int bj = b - bi * (bi + 1) / 2;
    const int i0 = bi * BT;
    const int j0 = bj * BT;

    // sq norms: warp w handles 8 of the 64 rows
#pragma unroll
    for (int rr = 0; rr < 8; rr++) {
        int r = w * 8 + rr;
        int gr = (r < 32) ? (i0 + r) : (j0 + r - 32);
        const float* row = x + gr * D;
        float s = 0.f;
#pragma unroll
        for (int c = 0; c < 8; c++) { float v = row[lane + 32 * c]; s += v * v; }
#pragma unroll
        for (int o = 16; o > 0; o >>= 1) s += __shfl_down_sync(FULL, s, o);
        if (lane == 0) { if (r < 32) sqi[r] = s; else sqj[r - 32] = s; }
    }

    // GEMM: 2x2 register tile, k-major smem
    const int lr = t >> 3;
    const int lk = (t & 7) * 4;
    const int tx = t & 15;
    const int ty = t >> 4;

    float acc00 = 0.f, acc01 = 0.f, acc10 = 0.f, acc11 = 0.f;
    const float* pa = x + (i0 + lr) * D + lk;
    const float* pb = x + (j0 + lr) * D + lk;
    float4 va = *reinterpret_cast<const float4*>(pa);
    float4 vb = *reinterpret_cast<const float4*>(pb);

#pragma unroll
    for (int ch = 0; ch < D / BT; ch++) {
        __syncthreads();
        As[lk + 0][lr] = va.x; As[lk + 1][lr] = va.y;
        As[lk + 2][lr] = va.z; As[lk + 3][lr] = va.w;
        Bs[lk + 0][lr] = vb.x; Bs[lk + 1][lr] = vb.y;
        Bs[lk + 2][lr] = vb.z; Bs[lk + 3][lr] = vb.w;
        __syncthreads();
        if (ch < D / BT - 1) {
            va = *reinterpret_cast<const float4*>(pa + (ch + 1) * BT);
            vb = *reinterpret_cast<const float4*>(pb + (ch + 1) * BT);
        }
#pragma unroll
        for (int k = 0; k < BT; k++) {
            float2 a  = *reinterpret_cast<const float2*>(&As[k][2 * ty]);
            float2 bq = *reinterpret_cast<const float2*>(&Bs[k][2 * tx]);
            acc00 += a.x * bq.x; acc01 += a.x * bq.y;
            acc10 += a.y * bq.x; acc11 += a.y * bq.y;
        }
    }

    // epilogue: distances + mirror
    {
        const int ig = i0 + 2 * ty;
        const int jg = j0 + 2 * tx;
        const float si0 = sqi[2 * ty], si1 = sqi[2 * ty + 1];
        const float sj0 = sqj[2 * tx], sj1 = sqj[2 * tx + 1];

        float d00 = sqrtf(fmaxf(si0 + sj0 - 2.f * acc00, 1e-16f));
        float d01 = sqrtf(fmaxf(si0 + sj1 - 2.f * acc01, 1e-16f));
        float d10 = sqrtf(fmaxf(si1 + sj0 - 2.f * acc10, 1e-16f));
        float d11 = sqrtf(fmaxf(si1 + sj1 - 2.f * acc11, 1e-16f));

        *reinterpret_cast<float2*>(g_dist + (ig    ) * N + jg) = make_float2(d00, d01);
        *reinterpret_cast<float2*>(g_dist + (ig + 1) * N + jg) = make_float2(d10, d11);
        if (bi != bj) {
            g_dist[(jg    ) * N + ig    ] = d00;
            g_dist[(jg + 1) * N + ig    ] = d01;
            g_dist[(jg    ) * N + ig + 1] = d10;
            g_dist[(jg + 1) * N + ig + 1] = d11;
        }
    }

    // diagonal blocks: emit class member lists (classes 4*bi .. 4*bi+3)
    if (bi == bj) {
        __syncthreads();                           // As free after GEMM reads
        int* labs = reinterpret_cast<int*>(&As[0][0]);
        reinterpret_cast<int2*>(labs)[t] =
            reinterpret_cast<const int2*>(labels)[t];
        __syncthreads();
        if (w < 4) {
            int c = bi * 4 + w;
            int cnt = 0;
            for (int cb = 0; cb < 16; cb++) {
                int lv = labs[cb * 32 + lane];
                unsigned m = __ballot_sync(FULL, lv == c);
                if (lv == c) {
                    int slot = cnt + __popc(m & ((1u << lane) - 1u));
                    if (slot < 31) g_cls[c * 32 + 1 + slot] = cb * 32 + lane;
                }
                cnt += __popc(m);
            }
            if (lane == 0) g_cls[c * 32] = (cnt < 31) ? cnt : 31;
        }
    }
}

// ---------------------------------------------------------------------------
// Kernel 2: lean triplet with PDL prologue overlap + branch-free inner loop.
// ---------------------------------------------------------------------------
__global__ void __launch_bounds__(512)
triplet_kernel(const int* __restrict__ labels, float* __restrict__ out) {
    __shared__ int   cls_sm[32];
    __shared__ float pv_sm[32];
    __shared__ float sred[16];
    __shared__ float cred[16];

    const int a = blockIdx.x;         // anchor
    const int t = threadIdx.x;        // 0..511
    const int lane = t & 31;
    const int w = t >> 5;             // 0..15

    // --- pre-sync prologue: independent of dist results ---
    const int li = __ldg(&labels[a]);
    const bool neg = (__ldg(&labels[t]) != li);   // t==a -> false

    // wait for dist grid completion (HW event, no spinning)
    cudaGridDependencySynchronize();

    if (t < 32) cls_sm[t] = g_cls[li * 32 + t];
    __syncthreads();
    const int cnt = cls_sm[0];        // class member count (incl. anchor), <=31
    if (t < cnt) {
        int mem = cls_sm[1 + t];
        // poison the anchor's own slot: contributes exactly 0 in the loop
        pv_sm[t] = (mem == a) ? -1e30f : (g_dist[a * N + mem] + 1.0f);
    }
    // poison d for non-negative threads: v = pv - 1e30 < 0 -> contributes 0
    const float d = neg ? g_dist[a * N + t] : 1e30f;
    __syncthreads();

    float sum = 0.f, c = 0.f;
#pragma unroll 4
    for (int p = 0; p < cnt; p++) {
        float v = pv_sm[p] - d;
        sum += fmaxf(v, 0.f);
        if (v > 1e-16f) c += 1.f;
    }

    // deterministic block reduction (16 warps)
#pragma unroll
    for (int o = 16; o > 0; o >>= 1) {
        sum += __shfl_down_sync(FULL, sum, o);
        c   += __shfl_down_sync(FULL, c, o);
    }
    if (lane == 0) { sred[w] = sum; cred[w] = c; }
    __syncthreads();
    if (t == 0) {
        float s = 0.f, cc = 0.f;
#pragma unroll
        for (int k = 0; k < 16; k++) { s += sred[k]; cc += cred[k]; }
        g_psum[a] = s;
        g_pcnt[a] = cc;
        __threadfence();
        atomicAdd(&g_done, 1);        // fire-and-forget arrival
    }

    // dedicated final block: spin, then final reduce (R15-proven)
    if (a == NBLK_T - 1) {
        if (t == 0) {
            volatile int* p = &g_done;
            while (*p < NBLK_T) { __nanosleep(32); }
        }
        __syncthreads();
        __threadfence();              // acquire all partials

        float s = __ldcg(&g_psum[t]);
        float cc = __ldcg(&g_pcnt[t]);
#pragma unroll
        for (int o = 16; o > 0; o >>= 1) {
            s  += __shfl_down_sync(FULL, s, o);
            cc += __shfl_down_sync(FULL, cc, o);
        }
        if (lane == 0) { sred[w] = s; cred[w] = cc; }
        __syncthreads();
        if (t == 0) {
            float S = 0.f, C = 0.f;
#pragma unroll
            for (int k = 0; k < 16; k++) { S += sred[k]; C += cred[k]; }
            out[0] = S / (C + 1e-16f);
            g_done = 0;               // reset for next graph replay
        }
    }
}

// ---------------------------------------------------------------------------
extern "C" void kernel_launch(void* const* d_in, const int* in_sizes, int n_in,
                              void* d_out, int out_size) {
    const float* x      = (const float*)d_in[0];   // (512, 256) float32
    const int*   labels = (const int*)d_in[1];     // (512,) int32
    float* out = (float*)d_out;

    dist_kernel<<<NBLK_D, 256>>>(x, labels);

    // PDL launch: triplet prologue overlaps dist execution
    cudaLaunchConfig_t cfg = {};
    cfg.gridDim = dim3(NBLK_T);
    cfg.blockDim = dim3(512);
    cfg.dynamicSmemBytes = 0;
    cfg.stream = 0;
    cudaLaunchAttribute at[1];
    at[0].id = cudaLaunchAttributeProgrammaticStreamSerialization;
    at[0].val.programmaticStreamSerializationAllowed = 1;
    cfg.attrs = at;
    cfg.numAttrs = 1;
    cudaLaunchKernelEx(&cfg, triplet_kernel, labels, out);
}